// round 9
// baseline (speedup 1.0000x reference)
#include <cuda_runtime.h>
#include <cuda_bf16.h>
#include <mma.h>
#include <math.h>
#include <stdint.h>

using namespace nvcuda;

#define NN 16384
#define BATCH 32
#define SEQ 512
#define HIDDIM 768
#define CH 32
#define VSZ 8192
#define LAB 10

// ---------------- device scratch ----------------
__device__ float g_h1[NN*CH];
__device__ float g_as1[NN*2];
__device__ float g_ad1[NN*2];
__device__ float4 g_ew4[NN];
__device__ __nv_bfloat16 g_W1hi[CH*HIDDIM];   // [n][k], ldm=768
__device__ __nv_bfloat16 g_W1lo[CH*HIDDIM];
__device__ float g_w2s[CH];
__device__ float g_w2d[CH];
__device__ float g_zpart[2][BATCH][8][CH];
__device__ float g_outv[64*HIDDIM];
__device__ float g_loss;
__device__ int   g_ticket2;
__device__ int   g_ticket3;

__device__ __forceinline__ float lrelu(float x){ return x > 0.f ? x : 0.2f*x; }

// ================= K0: convert W1 -> bf16 hi/lo (transposed) + prep ==========
// 13 blocks x 256: blocks 0..11 convert, block 12 does w2s/w2d + ticket init
__global__ void __launch_bounds__(256)
k0_prep(const float* __restrict__ W1, const float* __restrict__ W2,
        const float* __restrict__ att_src2, const float* __restrict__ att_dst2) {
    if (blockIdx.x == 12) {
        int lane = threadIdx.x & 31, w = threadIdx.x >> 5;
        if (threadIdx.x == 0) { g_loss = 0.f; g_ticket2 = 0; g_ticket3 = 0; }
        for (int c = w; c < CH; c += 8) {
            float ss = 0.f, sd = 0.f;
            for (int k = lane; k < HIDDIM; k += 32) {
                float wv = W2[c*HIDDIM + k];
                ss += wv * att_src2[k];
                sd += wv * att_dst2[k];
            }
            #pragma unroll
            for (int o = 16; o; o >>= 1) {
                ss += __shfl_xor_sync(0xffffffffu, ss, o);
                sd += __shfl_xor_sync(0xffffffffu, sd, o);
            }
            if (!lane) { g_w2s[c] = ss; g_w2d[c] = sd; }
        }
        return;
    }
    #pragma unroll
    for (int q = 0; q < 8; q++) {
        int e = blockIdx.x*2048 + q*256 + threadIdx.x;   // 0..24575
        int n = e & 31, k = e >> 5;
        float wv = W1[k*CH + n];
        __nv_bfloat16 hi = __float2bfloat16(wv);
        g_W1hi[n*HIDDIM + k] = hi;
        g_W1lo[n*HIDDIM + k] = __float2bfloat16(wv - __bfloat162float(hi));
    }
}

// ================= K1: h1 = feat@W1, WMMA bf16 4-term split, K-split x2 ======
// grid 544: blocks 0..511 GEMM tiles (32 rows, 8 warps = 4 tiles x 2 K-halves);
//           512..543 EM gather
__global__ void __launch_bounds__(256, 4)
k1_wmma(const float* __restrict__ feat,
        const float* __restrict__ att_src1, const float* __restrict__ att_dst1,
        const int* __restrict__ tokA, const int* __restrict__ tokB,
        const float* __restrict__ EM) {
    if (blockIdx.x >= 512) {
        int gb = blockIdx.x - 512;
        #pragma unroll
        for (int j = 0; j < 2; j++) {
            int i = gb*512 + j*256 + threadIdx.x;
            int pos = i & (SEQ-1);
            bool hasP = pos > 0, hasN = pos < SEQ-1;
            int ta = tokA[i], tb = tokB[i];
            float4 v;
            v.x = hasP ? EM[tokA[i-1]*VSZ + ta] : 0.f;
            v.y = hasN ? EM[tokA[i+1]*VSZ + ta] : 0.f;
            v.z = hasP ? EM[tokB[i-1]*VSZ + tb] : 0.f;
            v.w = hasN ? EM[tokB[i+1]*VSZ + tb] : 0.f;
            g_ew4[i] = v;
        }
        return;
    }

    // A smem: 32 rows x 160 cols bf16 (cols 0-63 = K-half0 chunk, 80-143 = K-half1 chunk)
    __shared__ union {
        struct { __nv_bfloat16 Ahi[32][160]; __nv_bfloat16 Alo[32][160]; } s;
        float Cs[2][32][36];
    } u;
    __shared__ float sAs[CH], sAd[CH];

    int tid = threadIdx.x, wid = tid >> 5;
    int rowBase = blockIdx.x * 32;
    if (tid < CH) { sAs[tid] = att_src1[tid]; sAd[tid] = att_dst1[tid]; }

    int tile = wid >> 1, khalf = wid & 1;
    int rg = tile >> 1, ct = tile & 1;
    int kw = khalf * 384;

    wmma::fragment<wmma::accumulator, 16, 16, 16, float> acc;
    wmma::fill_fragment(acc, 0.f);

    // staging map: e = q*256+tid; r = e>>5; c4 = e&31
    // c4 < 16 -> half0: src col s*64 + c4*4,       dst col c4*4
    // c4 >=16 -> half1: src col 384 + s*64 + ..,   dst col 80 + (c4-16)*4
    float4 va[4];
    #pragma unroll
    for (int q = 0; q < 4; q++) {
        int e = q*256 + tid, r = e >> 5, c4 = e & 31;
        int src = (c4 < 16) ? (c4*4) : (384 + (c4-16)*4);
        va[q] = *(const float4*)&feat[(size_t)(rowBase + r)*HIDDIM + src];
    }

    for (int s = 0; s < 6; s++) {
        // stage prefetched superchunk
        #pragma unroll
        for (int q = 0; q < 4; q++) {
            int e = q*256 + tid, r = e >> 5, c4 = e & 31;
            int dst = (c4 < 16) ? (c4*4) : (80 + (c4-16)*4);
            float4 v = va[q];
            __nv_bfloat162 h01 = __floats2bfloat162_rn(v.x, v.y);
            __nv_bfloat162 h23 = __floats2bfloat162_rn(v.z, v.w);
            *(__nv_bfloat162*)&u.s.Ahi[r][dst]   = h01;
            *(__nv_bfloat162*)&u.s.Ahi[r][dst+2] = h23;
            float lx = v.x - __low2float(h01),  ly = v.y - __high2float(h01);
            float lz = v.z - __low2float(h23),  lw = v.w - __high2float(h23);
            *(__nv_bfloat162*)&u.s.Alo[r][dst]   = __floats2bfloat162_rn(lx, ly);
            *(__nv_bfloat162*)&u.s.Alo[r][dst+2] = __floats2bfloat162_rn(lz, lw);
        }
        __syncthreads();

        // prefetch next superchunk (overlaps MMA)
        if (s < 5) {
            #pragma unroll
            for (int q = 0; q < 4; q++) {
                int e = q*256 + tid, r = e >> 5, c4 = e & 31;
                int src = (c4 < 16) ? ((s+1)*64 + c4*4) : (384 + (s+1)*64 + (c4-16)*4);
                va[q] = *(const float4*)&feat[(size_t)(rowBase + r)*HIDDIM + src];
            }
        }

        // MMA: this warp's 16x16 tile over its K-half chunk (B direct from global)
        const __nv_bfloat16* bh = g_W1hi + (size_t)(ct*16)*HIDDIM + kw + s*64;
        const __nv_bfloat16* bl = g_W1lo + (size_t)(ct*16)*HIDDIM + kw + s*64;
        #pragma unroll
        for (int kk = 0; kk < 4; kk++) {
            wmma::fragment<wmma::matrix_a, 16, 16, 16, __nv_bfloat16, wmma::row_major> a_hi, a_lo;
            wmma::load_matrix_sync(a_hi, &u.s.Ahi[rg*16][khalf*80 + kk*16], 160);
            wmma::load_matrix_sync(a_lo, &u.s.Alo[rg*16][khalf*80 + kk*16], 160);
            wmma::fragment<wmma::matrix_b, 16, 16, 16, __nv_bfloat16, wmma::col_major> b_hi, b_lo;
            wmma::load_matrix_sync(b_hi, bh + kk*16, HIDDIM);
            wmma::load_matrix_sync(b_lo, bl + kk*16, HIDDIM);
            wmma::mma_sync(acc, a_hi, b_hi, acc);
            wmma::mma_sync(acc, a_hi, b_lo, acc);
            wmma::mma_sync(acc, a_lo, b_hi, acc);
            wmma::mma_sync(acc, a_lo, b_lo, acc);
        }
        __syncthreads();
    }

    // epilogue: dump both K-half partials, sum, write h1 + attention dots
    wmma::store_matrix_sync(&u.Cs[khalf][rg*16][ct*16], acc, 36, wmma::mem_row_major);
    __syncthreads();
    if (tid < 32) {
        int r = rowBase + tid;
        float ss0 = 0.f, sd0 = 0.f, ss1 = 0.f, sd1 = 0.f;
        #pragma unroll
        for (int q = 0; q < 8; q++) {
            float4 v = { u.Cs[0][tid][q*4+0] + u.Cs[1][tid][q*4+0],
                         u.Cs[0][tid][q*4+1] + u.Cs[1][tid][q*4+1],
                         u.Cs[0][tid][q*4+2] + u.Cs[1][tid][q*4+2],
                         u.Cs[0][tid][q*4+3] + u.Cs[1][tid][q*4+3] };
            *(float4*)&g_h1[r*CH + q*4] = v;
            float ps = v.x*sAs[q*4+0] + v.y*sAs[q*4+1] + v.z*sAs[q*4+2] + v.w*sAs[q*4+3];
            float pd = v.x*sAd[q*4+0] + v.y*sAd[q*4+1] + v.z*sAd[q*4+2] + v.w*sAd[q*4+3];
            if (q < 4) { ss0 += ps; sd0 += pd; } else { ss1 += ps; sd1 += pd; }
        }
        g_as1[r*2 + 0] = ss0; g_ad1[r*2 + 0] = sd0;
        g_as1[r*2 + 1] = ss1; g_ad1[r*2 + 1] = sd1;
    }
}

// ================= KMID: conv1 + conv2 + pool partials, 64-node chunks ========
__global__ void __launch_bounds__(256)
kmid(const float* __restrict__ b1) {
    __shared__ float r_s[2][66][32];
    __shared__ float as2_s[2][66], ad2_s[2][66];
    __shared__ float red[2][8][32];

    int blk = blockIdx.x;
    int b = blk >> 3, q = blk & 7;
    int p0 = q * 64;
    int base = b * SEQ;
    int t = threadIdx.x, w = t >> 5, lane = t & 31;
    int head = lane >> 4;
    float bb = b1[lane];
    float ws2 = g_w2s[lane], wd2 = g_w2d[lane];

    for (int li = w; li < 66; li += 8) {
        int n = p0 - 1 + li;
        if (n < 0 || n >= SEQ) continue;
        int i = base + n;
        bool hasP = n > 0, hasN = n < SEQ-1;
        float adi = g_ad1[i*2 + head];
        float es = lrelu(g_as1[i*2 + head] + adi);
        float ep = hasP ? lrelu(g_as1[(i-1)*2 + head] + adi) : -1e30f;
        float en = hasN ? lrelu(g_as1[(i+1)*2 + head] + adi) : -1e30f;
        float m  = fmaxf(es, fmaxf(ep, en));
        float xs = expf(es - m);
        float xp = hasP ? expf(ep - m) : 0.f;
        float xn = hasN ? expf(en - m) : 0.f;
        float inv = 1.f / (xs + xp + xn + 1e-16f);
        float as_ = xs*inv, ap = xp*inv, an = xn*inv;

        float4 ewv = g_ew4[i];
        float hp = hasP ? g_h1[(i-1)*CH + lane] : 0.f;
        float hs = g_h1[i*CH + lane];
        float hn = hasN ? g_h1[(i+1)*CH + lane] : 0.f;

        float r1v = fmaxf(0.f, ap*ewv.x*hp + as_*hs + an*ewv.y*hn + bb);
        float r2v = fmaxf(0.f, ap*ewv.z*hp + as_*hs + an*ewv.w*hn + bb);
        r_s[0][li][lane] = r1v;
        r_s[1][li][lane] = r2v;

        float v0 = r1v*ws2, v1 = r1v*wd2, v2 = r2v*ws2, v3 = r2v*wd2;
        #pragma unroll
        for (int o = 16; o; o >>= 1) {
            v0 += __shfl_xor_sync(0xffffffffu, v0, o);
            v1 += __shfl_xor_sync(0xffffffffu, v1, o);
            v2 += __shfl_xor_sync(0xffffffffu, v2, o);
            v3 += __shfl_xor_sync(0xffffffffu, v3, o);
        }
        if (!lane) {
            as2_s[0][li] = v0; ad2_s[0][li] = v1;
            as2_s[1][li] = v2; ad2_s[1][li] = v3;
        }
    }
    __syncthreads();

    float acc0 = 0.f, acc1 = 0.f;
    for (int ln = w; ln < 64; ln += 8) {
        int n = p0 + ln, sl = ln + 1;
        bool hasP = n > 0, hasN = n < SEQ-1;
        #pragma unroll
        for (int br = 0; br < 2; br++) {
            float adi = ad2_s[br][sl];
            float es = lrelu(as2_s[br][sl] + adi);
            float ep = hasP ? lrelu(as2_s[br][sl-1] + adi) : -1e30f;
            float en = hasN ? lrelu(as2_s[br][sl+1] + adi) : -1e30f;
            float m  = fmaxf(es, fmaxf(ep, en));
            float xs = expf(es - m);
            float xp = hasP ? expf(ep - m) : 0.f;
            float xn = hasN ? expf(en - m) : 0.f;
            float inv = 1.f / (xs + xp + xn + 1e-16f);
            float z = xs*inv * r_s[br][sl][lane];
            if (hasP) z += xp*inv * r_s[br][sl-1][lane];
            if (hasN) z += xn*inv * r_s[br][sl+1][lane];
            if (br == 0) acc0 += z; else acc1 += z;
        }
    }
    red[0][w][lane] = acc0;
    red[1][w][lane] = acc1;
    __syncthreads();
    if (w < 2) {
        float s = 0.f;
        #pragma unroll
        for (int x = 0; x < 8; x++) s += red[w][x][lane];
        g_zpart[w][b][q][lane] = s;
    }
}

// ================= K4: pooled GEMM + tanh + spin barrier (96) + tail ====
__global__ void __launch_bounds__(256)
k4_fused(const float* __restrict__ W2, const float* __restrict__ b2,
         const float* __restrict__ Wo1, const float* __restrict__ bo1,
         const float* __restrict__ Wo2, const float* __restrict__ bo2,
         const int* __restrict__ label, float* __restrict__ out, int out_size) {
    __shared__ union {
        struct {
            float zbar[8][32];
            float As[8][68];
            float Bs[64][68];
            float W2s[32][68];
        } g;
        struct {
            float prow[HIDDIM];
            float WoT[LAB][HIDDIM];
            float lg[16];
            float dotc[64], normc[64], sims[64];
        } tl;
    } u;

    int tid = threadIdx.x;
    int colBase = blockIdx.x * 64, rowBase = blockIdx.y * 8;

    {
        int i = tid >> 5, c = tid & 31;
        int rr = rowBase + i, br = rr >> 5, bq = rr & 31;
        float s = 0.f;
        #pragma unroll
        for (int qq = 0; qq < 8; qq++) s += g_zpart[br][bq][qq][c];
        u.g.zbar[i][c] = s * (1.f/512.f);
    }

    int ty = tid >> 5, tx = tid & 31;
    float acc[2] = {};
    for (int kb = 0; kb < HIDDIM; kb += 64) {
        #pragma unroll
        for (int qq = 0; qq < 16; qq++) {
            int e = qq*256 + tid; int k = e >> 6, c = e & 63;
            u.g.Bs[k][c] = Wo1[(size_t)(kb + k)*HIDDIM + colBase + c];
        }
        #pragma unroll
        for (int qq = 0; qq < 8; qq++) {
            int e = qq*256 + tid; int c = e >> 6, k = e & 63;
            u.g.W2s[c][k] = W2[(size_t)c*HIDDIM + kb + k];
        }
        __syncthreads();
        {
            int i = tid >> 5, kq = (tid & 31)*2;
            float a0 = b2[kb+kq+0], a1 = b2[kb+kq+1];
            #pragma unroll
            for (int c = 0; c < 32; c++) {
                float z = u.g.zbar[i][c];
                a0 += z * u.g.W2s[c][kq+0];
                a1 += z * u.g.W2s[c][kq+1];
            }
            u.g.As[i][kq+0] = a0; u.g.As[i][kq+1] = a1;
        }
        __syncthreads();
        #pragma unroll
        for (int kk = 0; kk < 64; kk++) {
            float a = u.g.As[ty][kk];
            float2 b2v = *(float2*)&u.g.Bs[kk][tx*2];
            acc[0] += a*b2v.x; acc[1] += a*b2v.y;
        }
        __syncthreads();
    }
    {
        int row = rowBase + ty;
        #pragma unroll
        for (int j = 0; j < 2; j++) {
            int col = colBase + tx*2 + j;
            g_outv[row*HIDDIM + col] = tanhf(acc[j] + bo1[col]);
        }
    }

    __threadfence();
    __syncthreads();
    if (tid == 0) {
        atomicAdd(&g_ticket2, 1);
        while (*(volatile int*)&g_ticket2 < 96) __nanosleep(64);
    }
    __syncthreads();
    __threadfence();

    int blk = blockIdx.y*12 + blockIdx.x;
    int w = tid >> 5, lane = tid & 31;
    int base = (out_size > 320) ? 1 : 0;
    int y = blk;

    if (y < 64) {
        for (int k = tid; k < HIDDIM; k += 256) {
            #pragma unroll
            for (int lab = 0; lab < LAB; lab++) u.tl.WoT[lab][k] = Wo2[k*LAB + lab];
        }
        int pr = (y & 1)*32 + (y >> 1);
        const float4* prg = (const float4*)&g_outv[pr*HIDDIM];
        for (int k = tid; k < HIDDIM/4; k += 256) ((float4*)u.tl.prow)[k] = prg[k];
        __syncthreads();

        const float4* orow4 = (const float4*)&g_outv[y*HIDDIM];
        for (int lab = w; lab < LAB; lab += 8) {
            float s = 0.f;
            const float4* wr = (const float4*)&u.tl.WoT[lab][0];
            #pragma unroll
            for (int i = 0; i < 6; i++) {
                float4 a = orow4[lane + 32*i];
                float4 bv = wr[lane + 32*i];
                s += a.x*bv.x + a.y*bv.y + a.z*bv.z + a.w*bv.w;
            }
            #pragma unroll
            for (int o = 16; o; o >>= 1) s += __shfl_xor_sync(0xffffffffu, s, o);
            if (!lane) u.tl.lg[lab] = s + bo2[lab];
        }

        for (int c = w; c < 64; c += 8) {
            int rc = (c & 1)*32 + (c >> 1);
            const float4* pc = (const float4*)&g_outv[rc*HIDDIM];
            float d = 0.f, nn = 0.f;
            #pragma unroll
            for (int i = 0; i < 6; i++) {
                float4 v = pc[lane + 32*i];
                float4 p = ((float4*)u.tl.prow)[lane + 32*i];
                d  += p.x*v.x + p.y*v.y + p.z*v.z + p.w*v.w;
                nn += v.x*v.x + v.y*v.y + v.z*v.z + v.w*v.w;
            }
            #pragma unroll
            for (int o = 16; o; o >>= 1) {
                d  += __shfl_xor_sync(0xffffffffu, d, o);
                nn += __shfl_xor_sync(0xffffffffu, nn, o);
            }
            if (!lane) { u.tl.dotc[c] = d; u.tl.normc[c] = nn; }
        }
        __syncthreads();

        if (tid == 0) {
            float m = -1e30f;
            #pragma unroll
            for (int j = 0; j < LAB; j++) m = fmaxf(m, u.tl.lg[j]);
            float e = 0.f;
            #pragma unroll
            for (int j = 0; j < LAB; j++) e += expf(u.tl.lg[j] - m);
            float lse = m + logf(e);
            float nll = -(u.tl.lg[label[y & 31]] - lse);
            atomicAdd(&g_loss, nll * (1.f/32.f));
        }
        if (y < 32 && tid < LAB) {
            int idx = base + y*LAB + tid;
            if (idx < out_size) out[idx] = u.tl.lg[tid];
        }
        if (tid < 64) {
            float invy = 1.f / fmaxf(sqrtf(u.tl.normc[y]), 1e-8f);
            float invc = 1.f / fmaxf(sqrtf(u.tl.normc[tid]), 1e-8f);
            float v = u.tl.dotc[tid] * invy * invc;
            if (tid == y) v -= 1e12f;
            u.tl.sims[tid] = v * 20.0f;
        }
        __syncthreads();
        if (tid < 32) {
            float a = u.tl.sims[tid], b2v = u.tl.sims[tid + 32];
            float m = fmaxf(a, b2v);
            #pragma unroll
            for (int o = 16; o; o >>= 1) m = fmaxf(m, __shfl_xor_sync(0xffffffffu, m, o));
            float e = expf(a - m) + expf(b2v - m);
            #pragma unroll
            for (int o = 16; o; o >>= 1) e += __shfl_xor_sync(0xffffffffu, e, o);
            if (tid == 0) {
                float lse = m + logf(e);
                int partner = y ^ 1;
                atomicAdd(&g_loss, (-(u.tl.sims[partner] - lse)) * (1.f/64.f));
            }
        }
        __syncthreads();
    }

    if (tid == 0) {
        __threadfence();
        int tk = atomicAdd(&g_ticket3, 1);
        if (tk == 95 && base == 1) {
            out[0] = atomicAdd(&g_loss, 0.f);
        }
    }
}

extern "C" void kernel_launch(void* const* d_in, const int* in_sizes, int n_in,
                              void* d_out, int out_size) {
    const int*   src    = (const int*)  d_in[0];
    const int*   other  = (const int*)  d_in[1];
    const int*   label  = (const int*)  d_in[2];
    const float* feat   = (const float*)d_in[3];
    const float* EM     = (const float*)d_in[4];
    const float* W1     = (const float*)d_in[5];
    const float* asrc1  = (const float*)d_in[6];
    const float* adst1  = (const float*)d_in[7];
    const float* b1     = (const float*)d_in[8];
    const float* W2     = (const float*)d_in[9];
    const float* asrc2  = (const float*)d_in[10];
    const float* adst2  = (const float*)d_in[11];
    const float* b2     = (const float*)d_in[12];
    const float* Wo1    = (const float*)d_in[13];
    const float* bo1    = (const float*)d_in[14];
    const float* Wo2    = (const float*)d_in[15];
    const float* bo2    = (const float*)d_in[16];
    float* out = (float*)d_out;

    k0_prep<<<13, 256>>>(W1, W2, asrc2, adst2);
    k1_wmma<<<544, 256>>>(feat, asrc1, adst1, src, other, EM);
    kmid<<<256, 256>>>(b1);
    k4_fused<<<dim3(12, 8), 256>>>(W2, b2, Wo1, bo1, Wo2, bo2, label, out, out_size);
}

// round 10
// speedup vs baseline: 1.3403x; 1.3403x over previous
#include <cuda_runtime.h>
#include <cuda_bf16.h>
#include <mma.h>
#include <math.h>
#include <stdint.h>

using namespace nvcuda;

#define NN 16384
#define BATCH 32
#define SEQ 512
#define HIDDIM 768
#define CH 32
#define VSZ 8192
#define LAB 10

// ---------------- device scratch ----------------
__device__ float g_h1[NN*CH];
__device__ float g_as1[NN*2];
__device__ float g_ad1[NN*2];
__device__ float4 g_ew4[NN];
__device__ float g_w2s[CH];
__device__ float g_w2d[CH];
__device__ float g_zpart[2][BATCH][8][CH];
__device__ float g_outv[64*HIDDIM];
__device__ float g_loss;
__device__ int   g_ticket2;
__device__ int   g_ticket3;

__device__ __forceinline__ float lrelu(float x){ return x > 0.f ? x : 0.2f*x; }

// ================= K1: h1 = feat@W1 via WMMA bf16 4-term split ==============
// grid 289: blocks 0..255 GEMM tiles (64 rows each); 256 = prep; 257..288 = EM gather
// (round-7 version: measured 31.8us)
__global__ void __launch_bounds__(256)
k1_wmma(const float* __restrict__ feat, const float* __restrict__ W1,
        const float* __restrict__ W2,
        const float* __restrict__ att_src2, const float* __restrict__ att_dst2,
        const float* __restrict__ att_src1, const float* __restrict__ att_dst1,
        const int* __restrict__ tokA, const int* __restrict__ tokB,
        const float* __restrict__ EM) {
    if (blockIdx.x == 256) {
        int lane = threadIdx.x & 31, w = threadIdx.x >> 5;
        if (threadIdx.x == 0) { g_loss = 0.f; g_ticket2 = 0; g_ticket3 = 0; }
        for (int c = w; c < CH; c += 8) {
            float ss = 0.f, sd = 0.f;
            for (int k = lane; k < HIDDIM; k += 32) {
                float wv = W2[c*HIDDIM + k];
                ss += wv * att_src2[k];
                sd += wv * att_dst2[k];
            }
            #pragma unroll
            for (int o = 16; o; o >>= 1) {
                ss += __shfl_xor_sync(0xffffffffu, ss, o);
                sd += __shfl_xor_sync(0xffffffffu, sd, o);
            }
            if (!lane) { g_w2s[c] = ss; g_w2d[c] = sd; }
        }
        return;
    }
    if (blockIdx.x > 256) {
        int gb = blockIdx.x - 257;
        #pragma unroll
        for (int j = 0; j < 2; j++) {
            int i = gb*512 + j*256 + threadIdx.x;
            int pos = i & (SEQ-1);
            bool hasP = pos > 0, hasN = pos < SEQ-1;
            int ta = tokA[i], tb = tokB[i];
            float4 v;
            v.x = hasP ? EM[tokA[i-1]*VSZ + ta] : 0.f;
            v.y = hasN ? EM[tokA[i+1]*VSZ + ta] : 0.f;
            v.z = hasP ? EM[tokB[i-1]*VSZ + tb] : 0.f;
            v.w = hasN ? EM[tokB[i+1]*VSZ + tb] : 0.f;
            g_ew4[i] = v;
        }
        return;
    }

    // ---- GEMM tile: 64 rows x 32 cols, register-prefetch double buffering ----
    __shared__ union {
        struct {
            __nv_bfloat16 Ahi[64][72];
            __nv_bfloat16 Alo[64][72];
            __nv_bfloat16 Bhi[32][72];
            __nv_bfloat16 Blo[32][72];
        } s;
        float Cs[64][36];
    } u;
    __shared__ float sAs[CH], sAd[CH];

    int tid = threadIdx.x, wid = tid >> 5;
    int rowBase = blockIdx.x * 64;
    if (tid < CH) { sAs[tid] = att_src1[tid]; sAd[tid] = att_dst1[tid]; }

    int rg = wid >> 1, ct = wid & 1;     // warp -> 16x16 C tile
    wmma::fragment<wmma::accumulator, 16, 16, 16, float> acc;
    wmma::fill_fragment(acc, 0.f);

    int ar = tid >> 2;                    // A row this thread stages (0..63)
    int af = tid & 3;                     // float4 group
    const float* frow = &feat[(size_t)(rowBase + ar)*HIDDIM];

    // prefetch chunk 0
    float4 va[4];
    float  vb[8];
    #pragma unroll
    for (int j = 0; j < 4; j++) va[j] = *(const float4*)&frow[(af + j*4)*4];
    #pragma unroll
    for (int q = 0; q < 8; q++) {
        int e = q*256 + tid;
        vb[q] = W1[(size_t)(e >> 5)*CH + (e & 31)];
    }

    for (int kb = 0; kb < HIDDIM; kb += 64) {
        // ---- stage prefetched chunk into smem (fp32 -> hi/lo bf16) ----
        #pragma unroll
        for (int j = 0; j < 4; j++) {
            float4 v = va[j];
            int col = (af + j*4)*4;
            __nv_bfloat162 h01 = __floats2bfloat162_rn(v.x, v.y);
            __nv_bfloat162 h23 = __floats2bfloat162_rn(v.z, v.w);
            *(__nv_bfloat162*)&u.s.Ahi[ar][col]   = h01;
            *(__nv_bfloat162*)&u.s.Ahi[ar][col+2] = h23;
            float lx = v.x - __low2float(h01),  ly = v.y - __high2float(h01);
            float lz = v.z - __low2float(h23),  lw = v.w - __high2float(h23);
            *(__nv_bfloat162*)&u.s.Alo[ar][col]   = __floats2bfloat162_rn(lx, ly);
            *(__nv_bfloat162*)&u.s.Alo[ar][col+2] = __floats2bfloat162_rn(lz, lw);
        }
        #pragma unroll
        for (int q = 0; q < 8; q++) {
            int e = q*256 + tid;
            int k = e >> 5, n = e & 31;
            float wv = vb[q];
            __nv_bfloat16 hi = __float2bfloat16(wv);
            float lo = wv - __bfloat162float(hi);
            u.s.Bhi[n][k] = hi;
            u.s.Blo[n][k] = __float2bfloat16(lo);
        }
        __syncthreads();

        // ---- prefetch next chunk (overlaps with MMA below) ----
        if (kb + 64 < HIDDIM) {
            #pragma unroll
            for (int j = 0; j < 4; j++)
                va[j] = *(const float4*)&frow[kb + 64 + (af + j*4)*4];
            #pragma unroll
            for (int q = 0; q < 8; q++) {
                int e = q*256 + tid;
                vb[q] = W1[(size_t)(kb + 64 + (e >> 5))*CH + (e & 31)];
            }
        }

        // ---- MMA: this warp's 16x16 tile, 4 k-steps x 4 split terms ----
        #pragma unroll
        for (int kk = 0; kk < 4; kk++) {
            wmma::fragment<wmma::matrix_a, 16, 16, 16, __nv_bfloat16, wmma::row_major> a_hi, a_lo;
            wmma::load_matrix_sync(a_hi, &u.s.Ahi[rg*16][kk*16], 72);
            wmma::load_matrix_sync(a_lo, &u.s.Alo[rg*16][kk*16], 72);
            wmma::fragment<wmma::matrix_b, 16, 16, 16, __nv_bfloat16, wmma::col_major> b_hi, b_lo;
            wmma::load_matrix_sync(b_hi, &u.s.Bhi[ct*16][kk*16], 72);
            wmma::load_matrix_sync(b_lo, &u.s.Blo[ct*16][kk*16], 72);
            wmma::mma_sync(acc, a_hi, b_hi, acc);
            wmma::mma_sync(acc, a_hi, b_lo, acc);
            wmma::mma_sync(acc, a_lo, b_hi, acc);
            wmma::mma_sync(acc, a_lo, b_lo, acc);
        }
        __syncthreads();
    }

    // ---- epilogue ----
    wmma::store_matrix_sync(&u.Cs[rg*16][ct*16], acc, 36, wmma::mem_row_major);
    __syncthreads();
    if (tid < 64) {
        int r = rowBase + tid;
        float ss0 = 0.f, sd0 = 0.f, ss1 = 0.f, sd1 = 0.f;
        #pragma unroll
        for (int q = 0; q < 8; q++) {
            float4 v = { u.Cs[tid][q*4+0], u.Cs[tid][q*4+1], u.Cs[tid][q*4+2], u.Cs[tid][q*4+3] };
            *(float4*)&g_h1[r*CH + q*4] = v;
            float ps = v.x*sAs[q*4+0] + v.y*sAs[q*4+1] + v.z*sAs[q*4+2] + v.w*sAs[q*4+3];
            float pd = v.x*sAd[q*4+0] + v.y*sAd[q*4+1] + v.z*sAd[q*4+2] + v.w*sAd[q*4+3];
            if (q < 4) { ss0 += ps; sd0 += pd; } else { ss1 += ps; sd1 += pd; }
        }
        g_as1[r*2 + 0] = ss0; g_ad1[r*2 + 0] = sd0;
        g_as1[r*2 + 1] = ss1; g_ad1[r*2 + 1] = sd1;
    }
}

// ================= KMID: conv1 + conv2 + pool partials, 64-node chunks ========
// grid 256 (32 seq x 8 chunks of 64), block 256
__global__ void __launch_bounds__(256)
kmid(const float* __restrict__ b1) {
    __shared__ float r_s[2][66][32];
    __shared__ float as2_s[2][66], ad2_s[2][66];
    __shared__ float red[2][8][32];

    int blk = blockIdx.x;
    int b = blk >> 3, q = blk & 7;
    int p0 = q * 64;
    int base = b * SEQ;
    int t = threadIdx.x, w = t >> 5, lane = t & 31;
    int head = lane >> 4;
    float bb = b1[lane];
    float ws2 = g_w2s[lane], wd2 = g_w2d[lane];

    for (int li = w; li < 66; li += 8) {
        int n = p0 - 1 + li;
        if (n < 0 || n >= SEQ) continue;
        int i = base + n;
        bool hasP = n > 0, hasN = n < SEQ-1;
        float adi = g_ad1[i*2 + head];
        float es = lrelu(g_as1[i*2 + head] + adi);
        float ep = hasP ? lrelu(g_as1[(i-1)*2 + head] + adi) : -1e30f;
        float en = hasN ? lrelu(g_as1[(i+1)*2 + head] + adi) : -1e30f;
        float m  = fmaxf(es, fmaxf(ep, en));
        float xs = expf(es - m);
        float xp = hasP ? expf(ep - m) : 0.f;
        float xn = hasN ? expf(en - m) : 0.f;
        float inv = 1.f / (xs + xp + xn + 1e-16f);
        float as_ = xs*inv, ap = xp*inv, an = xn*inv;

        float4 ewv = g_ew4[i];
        float hp = hasP ? g_h1[(i-1)*CH + lane] : 0.f;
        float hs = g_h1[i*CH + lane];
        float hn = hasN ? g_h1[(i+1)*CH + lane] : 0.f;

        float r1v = fmaxf(0.f, ap*ewv.x*hp + as_*hs + an*ewv.y*hn + bb);
        float r2v = fmaxf(0.f, ap*ewv.z*hp + as_*hs + an*ewv.w*hn + bb);
        r_s[0][li][lane] = r1v;
        r_s[1][li][lane] = r2v;

        float v0 = r1v*ws2, v1 = r1v*wd2, v2 = r2v*ws2, v3 = r2v*wd2;
        #pragma unroll
        for (int o = 16; o; o >>= 1) {
            v0 += __shfl_xor_sync(0xffffffffu, v0, o);
            v1 += __shfl_xor_sync(0xffffffffu, v1, o);
            v2 += __shfl_xor_sync(0xffffffffu, v2, o);
            v3 += __shfl_xor_sync(0xffffffffu, v3, o);
        }
        if (!lane) {
            as2_s[0][li] = v0; ad2_s[0][li] = v1;
            as2_s[1][li] = v2; ad2_s[1][li] = v3;
        }
    }
    __syncthreads();

    float acc0 = 0.f, acc1 = 0.f;
    for (int ln = w; ln < 64; ln += 8) {
        int n = p0 + ln, sl = ln + 1;
        bool hasP = n > 0, hasN = n < SEQ-1;
        #pragma unroll
        for (int br = 0; br < 2; br++) {
            float adi = ad2_s[br][sl];
            float es = lrelu(as2_s[br][sl] + adi);
            float ep = hasP ? lrelu(as2_s[br][sl-1] + adi) : -1e30f;
            float en = hasN ? lrelu(as2_s[br][sl+1] + adi) : -1e30f;
            float m  = fmaxf(es, fmaxf(ep, en));
            float xs = expf(es - m);
            float xp = hasP ? expf(ep - m) : 0.f;
            float xn = hasN ? expf(en - m) : 0.f;
            float inv = 1.f / (xs + xp + xn + 1e-16f);
            float z = xs*inv * r_s[br][sl][lane];
            if (hasP) z += xp*inv * r_s[br][sl-1][lane];
            if (hasN) z += xn*inv * r_s[br][sl+1][lane];
            if (br == 0) acc0 += z; else acc1 += z;
        }
    }
    red[0][w][lane] = acc0;
    red[1][w][lane] = acc1;
    __syncthreads();
    if (w < 2) {
        float s = 0.f;
        #pragma unroll
        for (int x = 0; x < 8; x++) s += red[w][x][lane];
        g_zpart[w][b][q][lane] = s;
    }
}

// ================= K4: pooled GEMM + tanh + spin barrier (192) + tail ====
// grid dim3(24,8) = 192 blocks, block 256; 32-col x 8-row output tiles
__global__ void __launch_bounds__(256)
k4_fused(const float* __restrict__ W2, const float* __restrict__ b2,
         const float* __restrict__ Wo1, const float* __restrict__ bo1,
         const float* __restrict__ Wo2, const float* __restrict__ bo2,
         const int* __restrict__ label, float* __restrict__ out, int out_size) {
    __shared__ union {
        struct {
            float zbar[8][32];
            float As[8][68];
            float Bs[64][36];
            float W2s[32][68];
        } g;
        struct {
            float prow[HIDDIM];
            float WoT[LAB][HIDDIM];
            float lg[16];
            float dotc[64], normc[64], sims[64];
        } tl;
    } u;

    int tid = threadIdx.x;
    int colBase = blockIdx.x * 32, rowBase = blockIdx.y * 8;

    // zbar for this block's 8 rows (1 entry per thread)
    {
        int i = tid >> 5, c = tid & 31;
        int rr = rowBase + i, br = rr >> 5, bq = rr & 31;
        float s = 0.f;
        #pragma unroll
        for (int qq = 0; qq < 8; qq++) s += g_zpart[br][bq][qq][c];
        u.g.zbar[i][c] = s * (1.f/512.f);
    }

    int ty = tid >> 5, tx = tid & 31;   // 8 rows x 32 cols, 1 output/thread
    float acc = 0.f;
    for (int kb = 0; kb < HIDDIM; kb += 64) {
        // Bs[k][c]: 64 x 32 tile of Wo1
        #pragma unroll
        for (int qq = 0; qq < 8; qq++) {
            int e = qq*256 + tid; int k = e >> 5, c = e & 31;
            u.g.Bs[k][c] = Wo1[(size_t)(kb + k)*HIDDIM + colBase + c];
        }
        // W2s[c][k]: 32 x 64 tile of W2
        #pragma unroll
        for (int qq = 0; qq < 8; qq++) {
            int e = qq*256 + tid; int c = e >> 6, k = e & 63;
            u.g.W2s[c][k] = W2[(size_t)c*HIDDIM + kb + k];
        }
        __syncthreads();
        // As[i][k] = b2 + zbar[i] . W2s[:,k]  (2 k-cols per thread)
        {
            int i = tid >> 5, kq = (tid & 31)*2;
            float a0 = b2[kb+kq+0], a1 = b2[kb+kq+1];
            #pragma unroll
            for (int c = 0; c < 32; c++) {
                float z = u.g.zbar[i][c];
                a0 += z * u.g.W2s[c][kq+0];
                a1 += z * u.g.W2s[c][kq+1];
            }
            u.g.As[i][kq+0] = a0; u.g.As[i][kq+1] = a1;
        }
        __syncthreads();
        #pragma unroll
        for (int kk = 0; kk < 64; kk++)
            acc += u.g.As[ty][kk] * u.g.Bs[kk][tx];
        __syncthreads();
    }
    {
        int row = rowBase + ty;
        int col = colBase + tx;
        g_outv[row*HIDDIM + col] = tanhf(acc + bo1[col]);
    }

    // ---- device-wide barrier across the 192 co-resident blocks ----
    __threadfence();
    __syncthreads();
    if (tid == 0) {
        atomicAdd(&g_ticket2, 1);
        while (*(volatile int*)&g_ticket2 < 192) __nanosleep(64);
    }
    __syncthreads();
    __threadfence();

    int blk = blockIdx.y*24 + blockIdx.x;
    int w = tid >> 5, lane = tid & 31;
    int base = (out_size > 320) ? 1 : 0;
    int y = blk;

    if (y < 64) {
        for (int k = tid; k < HIDDIM; k += 256) {
            #pragma unroll
            for (int lab = 0; lab < LAB; lab++) u.tl.WoT[lab][k] = Wo2[k*LAB + lab];
        }
        int pr = (y & 1)*32 + (y >> 1);
        const float4* prg = (const float4*)&g_outv[pr*HIDDIM];
        for (int k = tid; k < HIDDIM/4; k += 256) ((float4*)u.tl.prow)[k] = prg[k];
        __syncthreads();

        const float4* orow4 = (const float4*)&g_outv[y*HIDDIM];
        for (int lab = w; lab < LAB; lab += 8) {
            float s = 0.f;
            const float4* wr = (const float4*)&u.tl.WoT[lab][0];
            #pragma unroll
            for (int i = 0; i < 6; i++) {
                float4 a = orow4[lane + 32*i];
                float4 bv = wr[lane + 32*i];
                s += a.x*bv.x + a.y*bv.y + a.z*bv.z + a.w*bv.w;
            }
            #pragma unroll
            for (int o = 16; o; o >>= 1) s += __shfl_xor_sync(0xffffffffu, s, o);
            if (!lane) u.tl.lg[lab] = s + bo2[lab];
        }

        for (int c = w; c < 64; c += 8) {
            int rc = (c & 1)*32 + (c >> 1);
            const float4* pc = (const float4*)&g_outv[rc*HIDDIM];
            float d = 0.f, nn = 0.f;
            #pragma unroll
            for (int i = 0; i < 6; i++) {
                float4 v = pc[lane + 32*i];
                float4 p = ((float4*)u.tl.prow)[lane + 32*i];
                d  += p.x*v.x + p.y*v.y + p.z*v.z + p.w*v.w;
                nn += v.x*v.x + v.y*v.y + v.z*v.z + v.w*v.w;
            }
            #pragma unroll
            for (int o = 16; o; o >>= 1) {
                d  += __shfl_xor_sync(0xffffffffu, d, o);
                nn += __shfl_xor_sync(0xffffffffu, nn, o);
            }
            if (!lane) { u.tl.dotc[c] = d; u.tl.normc[c] = nn; }
        }
        __syncthreads();

        if (tid == 0) {
            float m = -1e30f;
            #pragma unroll
            for (int j = 0; j < LAB; j++) m = fmaxf(m, u.tl.lg[j]);
            float e = 0.f;
            #pragma unroll
            for (int j = 0; j < LAB; j++) e += expf(u.tl.lg[j] - m);
            float lse = m + logf(e);
            float nll = -(u.tl.lg[label[y & 31]] - lse);
            atomicAdd(&g_loss, nll * (1.f/32.f));
        }
        if (y < 32 && tid < LAB) {
            int idx = base + y*LAB + tid;
            if (idx < out_size) out[idx] = u.tl.lg[tid];
        }
        if (tid < 64) {
            float invy = 1.f / fmaxf(sqrtf(u.tl.normc[y]), 1e-8f);
            float invc = 1.f / fmaxf(sqrtf(u.tl.normc[tid]), 1e-8f);
            float v = u.tl.dotc[tid] * invy * invc;
            if (tid == y) v -= 1e12f;
            u.tl.sims[tid] = v * 20.0f;
        }
        __syncthreads();
        if (tid < 32) {
            float a = u.tl.sims[tid], b2v = u.tl.sims[tid + 32];
            float m = fmaxf(a, b2v);
            #pragma unroll
            for (int o = 16; o; o >>= 1) m = fmaxf(m, __shfl_xor_sync(0xffffffffu, m, o));
            float e = expf(a - m) + expf(b2v - m);
            #pragma unroll
            for (int o = 16; o; o >>= 1) e += __shfl_xor_sync(0xffffffffu, e, o);
            if (tid == 0) {
                float lse = m + logf(e);
                int partner = y ^ 1;
                atomicAdd(&g_loss, (-(u.tl.sims[partner] - lse)) * (1.f/64.f));
            }
        }
        __syncthreads();
    }

    if (tid == 0) {
        __threadfence();
        int tk = atomicAdd(&g_ticket3, 1);
        if (tk == 191 && base == 1) {
            out[0] = atomicAdd(&g_loss, 0.f);
        }
    }
}

extern "C" void kernel_launch(void* const* d_in, const int* in_sizes, int n_in,
                              void* d_out, int out_size) {
    const int*   src    = (const int*)  d_in[0];
    const int*   other  = (const int*)  d_in[1];
    const int*   label  = (const int*)  d_in[2];
    const float* feat   = (const float*)d_in[3];
    const float* EM     = (const float*)d_in[4];
    const float* W1     = (const float*)d_in[5];
    const float* asrc1  = (const float*)d_in[6];
    const float* adst1  = (const float*)d_in[7];
    const float* b1     = (const float*)d_in[8];
    const float* W2     = (const float*)d_in[9];
    const float* asrc2  = (const float*)d_in[10];
    const float* adst2  = (const float*)d_in[11];
    const float* b2     = (const float*)d_in[12];
    const float* Wo1    = (const float*)d_in[13];
    const float* bo1    = (const float*)d_in[14];
    const float* Wo2    = (const float*)d_in[15];
    const float* bo2    = (const float*)d_in[16];
    float* out = (float*)d_out;

    k1_wmma<<<289, 256>>>(feat, W1, W2, asrc2, adst2, asrc1, adst1, src, other, EM);
    kmid<<<256, 256>>>(b1);
    k4_fused<<<dim3(24, 8), 256>>>(W2, b2, Wo1, bo1, Wo2, bo2, label, out, out_size);
}